// round 2
// baseline (speedup 1.0000x reference)
#include <cuda_runtime.h>

#define BB 8192
#define FF 32
#define EE 64
#define PP 496   // 32 choose 2

__global__ __launch_bounds__(256, 5)
void bilinear_pair_kernel(const float* __restrict__ x,
                          const float* __restrict__ W,
                          float* __restrict__ out)
{
    __shared__ float Ws[EE][EE];           // 16 KB   W[e][d]
    __shared__ float xs[FF][EE];           // 8 KB    x[b][f][e]
    __shared__ float xws[FF][EE];          // 8 KB    (x[b] @ W)[f][d]
    __shared__ unsigned int pairlut[PP];   // 2 KB    (i*EE)<<16 | (j*EE)

    const int b   = blockIdx.x;
    const int tid = threadIdx.x;

    // ---- build pair LUT once (2 iterations/thread) ----
    for (int p = tid; p < PP; p += 256) {
        int i = (int)((63.0f - sqrtf(3969.0f - 8.0f * (float)p)) * 0.5f);
        while (i * (63 - i) / 2 > p)           i--;
        while ((i + 1) * (62 - i) / 2 <= p)    i++;
        int j = p - i * (63 - i) / 2 + i + 1;
        pairlut[p] = ((unsigned int)(i * EE) << 16) | (unsigned int)(j * EE);
    }

    // ---- load W (4096 floats) and x[b] (2048 floats) as float4 ----
    {
        const float4* W4  = (const float4*)W;
        float4*       Ws4 = (float4*)&Ws[0][0];
        #pragma unroll
        for (int k = tid; k < EE * EE / 4; k += 256)
            Ws4[k] = W4[k];

        const float4* x4  = (const float4*)(x + (size_t)b * FF * EE);
        float4*       xs4 = (float4*)&xs[0][0];
        #pragma unroll
        for (int k = tid; k < FF * EE / 4; k += 256)
            xs4[k] = x4[k];
    }
    __syncthreads();

    // ---- xw[f][d] = sum_e xs[f][e] * Ws[e][d] ; 2048 outputs, 8/thread ----
    #pragma unroll
    for (int r = 0; r < 8; r++) {
        int idx = tid + r * 256;
        int row = idx >> 6;
        int col = idx & 63;
        float acc = 0.f;
        #pragma unroll
        for (int e = 0; e < EE; e++)
            acc = fmaf(xs[row][e], Ws[e][col], acc);
        xws[row][col] = acc;
    }
    __syncthreads();

    // ---- stream 496 pairs x 64 floats, coalesced float4 stores ----
    const float* xwsf = &xws[0][0];
    const float* xsf  = &xs[0][0];
    float4* out4 = (float4*)(out + (size_t)b * PP * EE);
    const int lane16 = (tid & 15) * 4;     // float offset within 64-wide row
    const int v16    = tid & 15;           // float4 index within row

    for (int p = tid >> 4; p < PP; p += 16) {
        unsigned int pr = pairlut[p];
        float4 a = *(const float4*)(xwsf + (pr >> 16) + lane16);
        float4 c = *(const float4*)(xsf  + (pr & 0xFFFF) + lane16);
        float4 r;
        r.x = a.x * c.x;
        r.y = a.y * c.y;
        r.z = a.z * c.z;
        r.w = a.w * c.w;
        // streaming store: output (1 GB) has zero reuse, evict-first
        __stcs(&out4[p * 16 + v16], r);
    }
}

extern "C" void kernel_launch(void* const* d_in, const int* in_sizes, int n_in,
                              void* d_out, int out_size)
{
    const float* x = (const float*)d_in[0];
    const float* W = (const float*)d_in[1];
    float*       o = (float*)d_out;
    bilinear_pair_kernel<<<BB, 256>>>(x, W, o);
}

// round 3
// speedup vs baseline: 1.2047x; 1.2047x over previous
#include <cuda_runtime.h>

#define BB 8192
#define FF 32
#define EE 64
#define PP 496   // 32 choose 2

__device__ __forceinline__ unsigned long long fma2(unsigned long long a,
                                                   unsigned long long b,
                                                   unsigned long long c) {
    unsigned long long d;
    asm("fma.rn.f32x2 %0, %1, %2, %3;" : "=l"(d) : "l"(a), "l"(b), "l"(c));
    return d;
}
__device__ __forceinline__ unsigned long long mul2(unsigned long long a,
                                                   unsigned long long b) {
    unsigned long long d;
    asm("mul.rn.f32x2 %0, %1, %2;" : "=l"(d) : "l"(a), "l"(b));
    return d;
}

__global__ __launch_bounds__(256)
void bilinear_pair_kernel(const float* __restrict__ x,
                          const float* __restrict__ W,
                          float* __restrict__ out)
{
    __shared__ float Ws[EE * EE];    // 16 KB  W[e*64+d]
    __shared__ float xs[FF * EE];    // 8 KB   x[b][f*64+e]
    __shared__ float xws[FF * EE];   // 8 KB   (x[b] @ W)

    const int b   = blockIdx.x;
    const int tid = threadIdx.x;

    // ---- load W (4096 floats) and x[b] (2048 floats) as float4 ----
    {
        const float4* W4  = (const float4*)W;
        float4*       Ws4 = (float4*)Ws;
        #pragma unroll
        for (int k = tid; k < EE * EE / 4; k += 256)
            Ws4[k] = W4[k];

        const float4* x4  = (const float4*)(x + (size_t)b * FF * EE);
        float4*       xs4 = (float4*)xs;
        #pragma unroll
        for (int k = tid; k < FF * EE / 4; k += 256)
            xs4[k] = x4[k];
    }
    __syncthreads();

    // ---- xw[f][d] = sum_e xs[f][e] * W[e][d]; 8 outputs/thread, f32x2 FMA ----
    {
        const int row = tid >> 3;            // 0..31
        const int v2  = (tid & 7) * 2;       // 16B-chunk index within 64-wide row
        const ulonglong2* Wsv = (const ulonglong2*)Ws;

        unsigned long long a0 = 0, a1 = 0, a2 = 0, a3 = 0;
        #pragma unroll 8
        for (int e = 0; e < EE; e++) {
            float xv = xs[row * EE + e];
            unsigned long long xv2;
            asm("mov.b64 %0, {%1, %1};" : "=l"(xv2) : "f"(xv));
            ulonglong2 w0 = Wsv[e * 16 + v2];
            ulonglong2 w1 = Wsv[e * 16 + v2 + 1];
            a0 = fma2(xv2, w0.x, a0);
            a1 = fma2(xv2, w0.y, a1);
            a2 = fma2(xv2, w1.x, a2);
            a3 = fma2(xv2, w1.y, a3);
        }
        ulonglong2* xwv = (ulonglong2*)(xws + row * EE) + v2;
        xwv[0] = make_ulonglong2(a0, a1);
        xwv[1] = make_ulonglong2(a2, a3);
    }
    __syncthreads();

    // ---- store 496 pairs: warp w owns i-strips {w, 15-w, 16+w, 31-w} (62 pairs) ----
    {
        const int wid  = tid >> 5;
        const int lane = tid & 31;
        const int half = lane >> 4;          // 0 or 1: which j parity this halfwarp does
        const int cv   = (lane & 15) * 4;    // float offset of this lane's 16B chunk
        float* outb = out + (size_t)b * PP * EE;

        #pragma unroll
        for (int s = 0; s < 4; s++) {
            const int i = (s == 0) ? wid
                        : (s == 1) ? 15 - wid
                        : (s == 2) ? 16 + wid
                        :            31 - wid;
            if (i >= FF - 1) continue;       // i=31 has no pairs
            const int pbase = i * (63 - i) / 2;
            // loop-invariant left operand: xw[i], this lane's chunk
            const ulonglong2 a = *(const ulonglong2*)(xws + i * EE + cv);

            #pragma unroll 4
            for (int j = i + 1 + half; j < FF; j += 2) {
                ulonglong2 c = *(const ulonglong2*)(xs + j * EE + cv);
                ulonglong2 r;
                r.x = mul2(a.x, c.x);
                r.y = mul2(a.y, c.y);
                const int p = pbase + (j - i - 1);
                // streaming store: 1 GB output, zero reuse — evict-first
                __stcs((float4*)(outb + (size_t)p * EE + cv), *(float4*)&r);
            }
        }
    }
}

extern "C" void kernel_launch(void* const* d_in, const int* in_sizes, int n_in,
                              void* d_out, int out_size)
{
    const float* x = (const float*)d_in[0];
    const float* W = (const float*)d_in[1];
    float*       o = (float*)d_out;
    bilinear_pair_kernel<<<BB, 256>>>(x, W, o);
}

// round 6
// speedup vs baseline: 2.3444x; 1.9461x over previous
#include <cuda_runtime.h>

#define BB 8192
#define FF 32
#define EE 64
#define PP 496   // 32 choose 2

__global__ __launch_bounds__(256)
void bilinear_pair_kernel(const float* __restrict__ x,
                          const float* __restrict__ W,
                          float* __restrict__ out)
{
    __shared__ float Ws[EE * EE];    // 16 KB  W[e*64+d]
    __shared__ float xs[FF * EE];    // 8 KB   x[b][f*64+e]
    __shared__ float xws[FF * EE];   // 8 KB   (x[b] @ W)

    const int b   = blockIdx.x;
    const int tid = threadIdx.x;

    // ---- load W (4096 floats) and x[b] (2048 floats) as float4 ----
    {
        const float4* W4  = (const float4*)W;
        float4*       Ws4 = (float4*)Ws;
        #pragma unroll
        for (int k = tid; k < EE * EE / 4; k += 256)
            Ws4[k] = W4[k];

        const float4* x4  = (const float4*)(x + (size_t)b * FF * EE);
        float4*       xs4 = (float4*)xs;
        #pragma unroll
        for (int k = tid; k < FF * EE / 4; k += 256)
            xs4[k] = x4[k];
    }
    __syncthreads();

    // ---- matmul: thread = 2 rows x 4 cols register tile ----
    // per e: 2 broadcast scalar LDS + 1 conflict-free LDS.128, 8 FMA
    {
        const int r0 = (tid >> 4) * 2;       // rows r0, r0+1
        const int c4 = (tid & 15) * 4;       // cols c4..c4+3
        float4 acc0 = make_float4(0.f, 0.f, 0.f, 0.f);
        float4 acc1 = make_float4(0.f, 0.f, 0.f, 0.f);

        #pragma unroll 16
        for (int e = 0; e < EE; e++) {
            float4 w = *(const float4*)(Ws + e * EE + c4);
            float  a0 = xs[r0 * EE + e];
            float  a1 = xs[(r0 + 1) * EE + e];
            acc0.x = fmaf(a0, w.x, acc0.x);
            acc0.y = fmaf(a0, w.y, acc0.y);
            acc0.z = fmaf(a0, w.z, acc0.z);
            acc0.w = fmaf(a0, w.w, acc0.w);
            acc1.x = fmaf(a1, w.x, acc1.x);
            acc1.y = fmaf(a1, w.y, acc1.y);
            acc1.z = fmaf(a1, w.z, acc1.z);
            acc1.w = fmaf(a1, w.w, acc1.w);
        }
        *(float4*)(xws + r0 * EE + c4)       = acc0;
        *(float4*)(xws + (r0 + 1) * EE + c4) = acc1;
    }
    __syncthreads();

    // ---- store 496 pairs: warp w owns i-strips {w, 15-w, 16+w, 31-w} (62 pairs) ----
    {
        const int wid  = tid >> 5;
        const int lane = tid & 31;
        const int half = lane >> 4;          // which j parity this half-warp handles
        const int cv   = (lane & 15) * 4;    // float offset of this lane's 16B chunk
        float* outb = out + (size_t)b * PP * EE;

        #pragma unroll
        for (int s = 0; s < 4; s++) {
            const int i = (s == 0) ? wid
                        : (s == 1) ? 15 - wid
                        : (s == 2) ? 16 + wid
                        :            31 - wid;
            if (i >= FF - 1) continue;       // i=31 has no pairs
            const int pbase = i * (63 - i) / 2;
            // loop-invariant left operand: xw[i], this lane's 16B chunk
            const float4 a = *(const float4*)(xws + i * EE + cv);

            #pragma unroll 4
            for (int j = i + 1 + half; j < FF; j += 2) {
                float4 c = *(const float4*)(xs + j * EE + cv);
                float4 r;
                r.x = a.x * c.x;
                r.y = a.y * c.y;
                r.z = a.z * c.z;
                r.w = a.w * c.w;
                const int p = pbase + (j - i - 1);
                // streaming store: 1 GB output, zero reuse — evict-first
                __stcs((float4*)(outb + (size_t)p * EE + cv), r);
            }
        }
    }
}

extern "C" void kernel_launch(void* const* d_in, const int* in_sizes, int n_in,
                              void* d_out, int out_size)
{
    const float* x = (const float*)d_in[0];
    const float* W = (const float*)d_in[1];
    float*       o = (float*)d_out;
    bilinear_pair_kernel<<<BB, 256>>>(x, W, o);
}